// round 15
// baseline (speedup 1.0000x reference)
#include <cuda_runtime.h>

// out = x^2 * 0.1 over 64M fp32. HBM-bound streaming kernel.
// v10: completes the MLP sweep — 16 front-batched float4 loads per thread
//      (MLP=16, ~80 regs, occ ~37%), exact-cover one-shot grid, streaming
//      cache hints. All loads independent, straight-line (no loop-carry).

#define THREADS 256
#define UNROLL  16

__global__ void __launch_bounds__(THREADS) poly_kernel_exact(
    const float4* __restrict__ x, float4* __restrict__ out)
{
    const int stride = gridDim.x * THREADS;
    const int base = blockIdx.x * THREADS + threadIdx.x;

    float4 v[UNROLL];
#pragma unroll
    for (int u = 0; u < UNROLL; u++)
        v[u] = __ldcs(&x[base + u * stride]);

#pragma unroll
    for (int u = 0; u < UNROLL; u++) {
        float4 r;
        r.x = v[u].x * v[u].x * 0.1f;
        r.y = v[u].y * v[u].y * 0.1f;
        r.z = v[u].z * v[u].z * 0.1f;
        r.w = v[u].w * v[u].w * 0.1f;
        __stcs(&out[base + u * stride], r);
    }
}

// Generic fallback (any n).
__global__ void __launch_bounds__(256) poly_kernel_generic(
    const float* __restrict__ x, float* __restrict__ out, int n)
{
    const int stride = gridDim.x * 256;
    for (int i = blockIdx.x * 256 + threadIdx.x; i < n; i += stride) {
        float v = x[i];
        out[i] = v * v * 0.1f;
    }
}

extern "C" void kernel_launch(void* const* d_in, const int* in_sizes, int n_in,
                              void* d_out, int out_size) {
    const float* x = (const float*)d_in[0];
    float* out = (float*)d_out;
    int n = in_sizes[0];

    const int per_block = THREADS * UNROLL;          // float4s per block = 4096
    if ((n % 4) == 0 && ((n / 4) % per_block) == 0) {
        int n4 = n / 4;
        int blocks = n4 / per_block;                 // 16M / 4096 = 4096
        poly_kernel_exact<<<blocks, THREADS>>>((const float4*)x, (float4*)out);
    } else {
        int blocks = (n + 255) / 256;
        if (blocks > 65536) blocks = 65536;
        poly_kernel_generic<<<blocks, 256>>>(x, out, n);
    }
}

// round 16
// speedup vs baseline: 1.0055x; 1.0055x over previous
#include <cuda_runtime.h>

// out = x^2 * 0.1 over 64M fp32. HBM-bound streaming kernel.
// v10: completes the MLP sweep — 16 front-batched float4 loads per thread
//      (MLP=16, ~80 regs, occ ~37%), exact-cover one-shot grid, streaming
//      cache hints. All loads independent, straight-line (no loop-carry).

#define THREADS 256
#define UNROLL  16

__global__ void __launch_bounds__(THREADS) poly_kernel_exact(
    const float4* __restrict__ x, float4* __restrict__ out)
{
    const int stride = gridDim.x * THREADS;
    const int base = blockIdx.x * THREADS + threadIdx.x;

    float4 v[UNROLL];
#pragma unroll
    for (int u = 0; u < UNROLL; u++)
        v[u] = __ldcs(&x[base + u * stride]);

#pragma unroll
    for (int u = 0; u < UNROLL; u++) {
        float4 r;
        r.x = v[u].x * v[u].x * 0.1f;
        r.y = v[u].y * v[u].y * 0.1f;
        r.z = v[u].z * v[u].z * 0.1f;
        r.w = v[u].w * v[u].w * 0.1f;
        __stcs(&out[base + u * stride], r);
    }
}

// Generic fallback (any n).
__global__ void __launch_bounds__(256) poly_kernel_generic(
    const float* __restrict__ x, float* __restrict__ out, int n)
{
    const int stride = gridDim.x * 256;
    for (int i = blockIdx.x * 256 + threadIdx.x; i < n; i += stride) {
        float v = x[i];
        out[i] = v * v * 0.1f;
    }
}

extern "C" void kernel_launch(void* const* d_in, const int* in_sizes, int n_in,
                              void* d_out, int out_size) {
    const float* x = (const float*)d_in[0];
    float* out = (float*)d_out;
    int n = in_sizes[0];

    const int per_block = THREADS * UNROLL;          // float4s per block = 4096
    if ((n % 4) == 0 && ((n / 4) % per_block) == 0) {
        int n4 = n / 4;
        int blocks = n4 / per_block;                 // 16M / 4096 = 4096
        poly_kernel_exact<<<blocks, THREADS>>>((const float4*)x, (float4*)out);
    } else {
        int blocks = (n + 255) / 256;
        if (blocks > 65536) blocks = 65536;
        poly_kernel_generic<<<blocks, 256>>>(x, out, n);
    }
}

// round 17
// speedup vs baseline: 1.0059x; 1.0004x over previous
#include <cuda_runtime.h>

// out = x^2 * 0.1 over 64M fp32. HBM-bound streaming kernel.
// v10: completes the MLP sweep — 16 front-batched float4 loads per thread
//      (MLP=16, ~80 regs, occ ~37%), exact-cover one-shot grid, streaming
//      cache hints. All loads independent, straight-line (no loop-carry).

#define THREADS 256
#define UNROLL  16

__global__ void __launch_bounds__(THREADS) poly_kernel_exact(
    const float4* __restrict__ x, float4* __restrict__ out)
{
    const int stride = gridDim.x * THREADS;
    const int base = blockIdx.x * THREADS + threadIdx.x;

    float4 v[UNROLL];
#pragma unroll
    for (int u = 0; u < UNROLL; u++)
        v[u] = __ldcs(&x[base + u * stride]);

#pragma unroll
    for (int u = 0; u < UNROLL; u++) {
        float4 r;
        r.x = v[u].x * v[u].x * 0.1f;
        r.y = v[u].y * v[u].y * 0.1f;
        r.z = v[u].z * v[u].z * 0.1f;
        r.w = v[u].w * v[u].w * 0.1f;
        __stcs(&out[base + u * stride], r);
    }
}

// Generic fallback (any n).
__global__ void __launch_bounds__(256) poly_kernel_generic(
    const float* __restrict__ x, float* __restrict__ out, int n)
{
    const int stride = gridDim.x * 256;
    for (int i = blockIdx.x * 256 + threadIdx.x; i < n; i += stride) {
        float v = x[i];
        out[i] = v * v * 0.1f;
    }
}

extern "C" void kernel_launch(void* const* d_in, const int* in_sizes, int n_in,
                              void* d_out, int out_size) {
    const float* x = (const float*)d_in[0];
    float* out = (float*)d_out;
    int n = in_sizes[0];

    const int per_block = THREADS * UNROLL;          // float4s per block = 4096
    if ((n % 4) == 0 && ((n / 4) % per_block) == 0) {
        int n4 = n / 4;
        int blocks = n4 / per_block;                 // 16M / 4096 = 4096
        poly_kernel_exact<<<blocks, THREADS>>>((const float4*)x, (float4*)out);
    } else {
        int blocks = (n + 255) / 256;
        if (blocks > 65536) blocks = 65536;
        poly_kernel_generic<<<blocks, 256>>>(x, out, n);
    }
}